// round 6
// baseline (speedup 1.0000x reference)
#include <cuda_runtime.h>

// AverageGridEncoder: scatter-mean of z over nearest grid cell, + latents.
// R6: persistent work-stealing gather (740 blocks = 148 SM x 5) to remove the
// 1.38-wave quantization that held occupancy at 47.6%. Flat unroll-4 stream
// per warp (8 cells = contiguous perm range) unchanged from R5.

#define P0 128
#define P1 128
#define NCELLS (P0 * P1)      // 16384
#define EMBED 128
#define MAXB 4
#define MAXN 100000
#define CPB 64                // cells per slice
#define PERMBUF 1024          // smem perm slice capacity (E[len]=391, sd~20)
#define GATHER_GRID 740       // 148 SMs x 5 blocks

__device__ int g_count[MAXB * NCELLS];
__device__ int g_offset[MAXB * NCELLS];
__device__ int g_cellrank[MAXB * MAXN];   // cell (14b) | rank<<14
__device__ int g_perm[MAXB * MAXN];
__device__ int g_ticket;                  // work-stealing cursor (reset in scan)

// Per-point cell + histogram; atomic return = rank within cell.
// 1/127 f32 step, IEEE divide + rintf (half-even) to match XLA round().
__global__ void hist_kernel(const float* __restrict__ x, int BN, int N) {
    int i = blockIdx.x * blockDim.x + threadIdx.x;
    if (i >= BN) return;
    float2 p = reinterpret_cast<const float2*>(x)[i];
    const float step = 1.0f / 127.0f;
    int i0 = (int)rintf(p.x / step);
    int i1 = (int)rintf(p.y / step);
    i0 = min(max(i0, 0), P0 - 1);
    i1 = min(max(i1, 0), P1 - 1);
    int cell = i0 * P1 + i1;
    int b = i / N;
    int rank = atomicAdd(&g_count[b * NCELLS + cell], 1);
    g_cellrank[i] = cell | (rank << 14);
}

// One block per batch: exclusive prefix over 16384 counts, shuffle scan.
// Also resets the gather ticket (runs before gather in stream order).
__global__ void scan_kernel() {
    __shared__ int warp_sums[32];
    int b = blockIdx.x;
    int t = threadIdx.x;
    if (b == 0 && t == 0) g_ticket = 0;
    int lane = t & 31, wid = t >> 5;
    int base = b * NCELLS;
    const int4* cnt4 = reinterpret_cast<const int4*>(g_count + base);
    int4* off4 = reinterpret_cast<int4*>(g_offset + base);
    int4 v[4];
    int sum = 0;
#pragma unroll
    for (int k = 0; k < 4; k++) {
        v[k] = cnt4[t * 4 + k];
        sum += v[k].x + v[k].y + v[k].z + v[k].w;
    }
    int inc = sum;                      // warp inclusive scan
#pragma unroll
    for (int d = 1; d < 32; d <<= 1) {
        int s = __shfl_up_sync(0xffffffffu, inc, d);
        if (lane >= d) inc += s;
    }
    if (lane == 31) warp_sums[wid] = inc;
    __syncthreads();
    if (wid == 0) {
        int ws = warp_sums[lane];
#pragma unroll
        for (int d = 1; d < 32; d <<= 1) {
            int s = __shfl_up_sync(0xffffffffu, ws, d);
            if (lane >= d) ws += s;
        }
        warp_sums[lane] = ws;
    }
    __syncthreads();
    int run = (wid > 0 ? warp_sums[wid - 1] : 0) + inc - sum;  // exclusive
#pragma unroll
    for (int k = 0; k < 4; k++) {
        int4 o;
        o.x = run; run += v[k].x;
        o.y = run; run += v[k].y;
        o.z = run; run += v[k].z;
        o.w = run; run += v[k].w;
        off4[t * 4 + k] = o;
    }
}

// Atomic-free scatter: slot = start[cell] + rank.
__global__ void scatter_kernel(int BN, int N) {
    int i = blockIdx.x * blockDim.x + threadIdx.x;
    if (i >= BN) return;
    int b = i / N;
    int n = i - b * N;
    unsigned v = (unsigned)g_cellrank[i];
    int cell = (int)(v & 16383u);
    int rank = (int)(v >> 14);
    int start = g_offset[b * NCELLS + cell];   // L2-resident
    g_perm[b * N + start + rank] = n;
}

// Persistent gather: blocks steal 64-cell slices via g_ticket until done.
// Slice: stage offsets + contiguous perm range in SMEM, then 8 warps x 8
// cells each run a flat unroll-4 z stream with warp-uniform boundary flush.
__global__ __launch_bounds__(256, 5) void gather_kernel(
        const float* __restrict__ z,
        const float* __restrict__ latents,
        float* __restrict__ out_x,
        float* __restrict__ out_z,
        int B, int N) {
    __shared__ int s_perm[PERMBUF];
    __shared__ int s_off[CPB + 1];
    __shared__ int s_slice;

    int t = threadIdx.x;
    int w = t >> 5, lane = t & 31;
    const int nslices = B * (NCELLS / CPB);
    const float4* lat4 = reinterpret_cast<const float4*>(latents);
    float4* outz4 = reinterpret_cast<float4*>(out_z);

    for (;;) {
        if (t == 0) s_slice = atomicAdd(&g_ticket, 1);
        __syncthreads();
        int slice = s_slice;
        if (slice >= nslices) break;

        int cellbase = slice * CPB;           // global cell index
        int b = cellbase / NCELLS;

        if (t <= CPB) {
            int g = cellbase + t;
            int v = (t == CPB && (g & (NCELLS - 1)) == 0) ? N : g_offset[g];
            s_off[t] = v;
            if (t < CPB) g_count[cellbase + t] = 0;   // reset for next replay
        }
        __syncthreads();

        int slice_start = s_off[0];
        int slice_len = s_off[CPB] - slice_start;
        const int* permb = g_perm + b * N + slice_start;
        bool in_smem = (slice_len <= PERMBUF);
        if (in_smem) {
            for (int i = t; i < slice_len; i += 256)
                s_perm[i] = permb[i];
        }
        __syncthreads();
        const int* psrc = in_smem ? (const int*)s_perm : permb;

        const float4* zb = reinterpret_cast<const float4*>(z) +
                           (size_t)b * N * (EMBED / 4);

        int lc = w * 8;                       // local cell
        const int last = lc + 8;
        int p = s_off[lc] - slice_start;
        const int wend = s_off[last] - slice_start;
        int cstart = p;
        int nend = s_off[lc + 1] - slice_start;
        float4 acc = make_float4(0.f, 0.f, 0.f, 0.f);
        float4 lat = lat4[(size_t)((cellbase + lc) & (NCELLS - 1)) * (EMBED / 4) + lane];

        auto flush = [&]() {
            int gc = cellbase + lc;
            int cnt = nend - cstart;
            float inv = (cnt > 0) ? (1.0f / (float)cnt) : 0.0f;
            float4 o;
            o.x = lat.x + acc.x * inv;
            o.y = lat.y + acc.y * inv;
            o.z = lat.z + acc.z * inv;
            o.w = lat.w + acc.w * inv;
            outz4[(size_t)gc * (EMBED / 4) + lane] = o;
            lc++;
            cstart = nend;
            if (lc < last) {
                nend = s_off[lc + 1] - slice_start;
                lat = lat4[(size_t)((cellbase + lc) & (NCELLS - 1)) * (EMBED / 4) + lane];
            }
            acc = make_float4(0.f, 0.f, 0.f, 0.f);
        };

        while (p + 4 <= wend) {
            int i0 = psrc[p];
            int i1 = psrc[p + 1];
            int i2 = psrc[p + 2];
            int i3 = psrc[p + 3];
            float4 v0 = zb[(size_t)i0 * (EMBED / 4) + lane];
            float4 v1 = zb[(size_t)i1 * (EMBED / 4) + lane];
            float4 v2 = zb[(size_t)i2 * (EMBED / 4) + lane];
            float4 v3 = zb[(size_t)i3 * (EMBED / 4) + lane];
            while (p == nend) flush();
            acc.x += v0.x; acc.y += v0.y; acc.z += v0.z; acc.w += v0.w; p++;
            while (p == nend) flush();
            acc.x += v1.x; acc.y += v1.y; acc.z += v1.z; acc.w += v1.w; p++;
            while (p == nend) flush();
            acc.x += v2.x; acc.y += v2.y; acc.z += v2.z; acc.w += v2.w; p++;
            while (p == nend) flush();
            acc.x += v3.x; acc.y += v3.y; acc.z += v3.z; acc.w += v3.w; p++;
        }
        while (p < wend) {
            int i0 = psrc[p];
            float4 v0 = zb[(size_t)i0 * (EMBED / 4) + lane];
            while (p == nend) flush();
            acc.x += v0.x; acc.y += v0.y; acc.z += v0.z; acc.w += v0.w; p++;
        }
        while (lc < last) flush();            // trailing (possibly empty) cells

        // x_grid: 64 cells x 2 floats, coalesced by 128 threads.
        if (t < 2 * CPB) {
            int gc = cellbase + (t >> 1);
            int cell = gc & (NCELLS - 1);
            int d = t & 1;
            int i0 = cell >> 7;
            int i1 = cell & (P1 - 1);
            const float step = 1.0f / 127.0f;
            out_x[(size_t)gc * 2 + d] = (float)(d == 0 ? i0 : i1) * step;
        }
        __syncthreads();   // protect s_off/s_perm before next slice refill
    }
}

extern "C" void kernel_launch(void* const* d_in, const int* in_sizes, int n_in,
                              void* d_out, int out_size) {
    // Identify inputs by size: z largest, x smallest, latents remaining.
    int ix = 0, iz = 0, il = 0;
    for (int i = 1; i < n_in; i++) {
        if (in_sizes[i] > in_sizes[iz]) iz = i;
        if (in_sizes[i] < in_sizes[ix]) ix = i;
    }
    for (int i = 0; i < n_in; i++)
        if (i != ix && i != iz) il = i;

    const float* x = (const float*)d_in[ix];
    const float* z = (const float*)d_in[iz];
    const float* latents = (const float*)d_in[il];

    int BN = in_sizes[ix] / 2;                        // B*N
    int B = out_size / (NCELLS * (2 + EMBED));
    if (B < 1) B = 1;
    int N = BN / B;

    float* out_x = (float*)d_out;                     // [B,128,128,2]
    float* out_z = (float*)d_out + (size_t)B * NCELLS * 2;  // [B,128,128,128]

    hist_kernel<<<(BN + 255) / 256, 256>>>(x, BN, N);
    scan_kernel<<<B, 1024>>>();
    scatter_kernel<<<(BN + 255) / 256, 256>>>(BN, N);
    int nslices = (B * NCELLS) / CPB;
    int grid = nslices < GATHER_GRID ? nslices : GATHER_GRID;
    gather_kernel<<<grid, 256>>>(z, latents, out_x, out_z, B, N);
}